// round 1
// baseline (speedup 1.0000x reference)
#include <cuda_runtime.h>

// Problem constants
#define HH 384
#define WW 384
#define CC 32
#define FF 32
#define KK 9
#define POS_PER_BLK 64        // x-positions per CTA (both batches handled together)
#define THREADS 256
#define SW_FLOATS (KK * CC * FF)          // 9216 floats = 36 KB
#define PIX_FLOATS (32 * 288 * 4)         // 32 pos-pairs x 288 kc x 4 (p0b0,p0b1,p1b0,p1b1)
#define SMEM_BYTES ((SW_FLOATS + PIX_FLOATS) * 4)   // 184320 B

__device__ __forceinline__ unsigned long long pack2(float lo, float hi) {
    unsigned long long r;
    asm("mov.b64 %0, {%1, %2};" : "=l"(r) : "f"(lo), "f"(hi));
    return r;
}
__device__ __forceinline__ void unpack2(unsigned long long v, float& lo, float& hi) {
    asm("mov.b64 {%0, %1}, %2;" : "=f"(lo), "=f"(hi) : "l"(v));
}
// Packed fp32x2 FMA (Blackwell): d = a*b + d elementwise on the two packed floats.
__device__ __forceinline__ void ffma2(unsigned long long& d, unsigned long long a,
                                      unsigned long long b) {
    asm("fma.rn.f32x2 %0, %1, %2, %0;" : "+l"(d) : "l"(a), "l"(b));
}

extern __shared__ float smem[];

__global__ __launch_bounds__(THREADS, 1)
void deform_conv_kernel(const float* __restrict__ x,
                        const float* __restrict__ off,
                        const float* __restrict__ kern,
                        const float* __restrict__ bias,
                        float* __restrict__ out)
{
    float* sW   = smem;                 // [288][32]  (kc-major, f contiguous)
    float* pixS = smem + SW_FLOATS;     // [pp(32)][kc(288)][4] : (p0b0,p0b1,p1b0,p1b1)

    const int tid  = threadIdx.x;
    const int lane = tid & 31;
    const int w    = tid >> 5;          // warp 0..7
    const int y    = blockIdx.y;
    const int xbase = blockIdx.x * POS_PER_BLK;

    // ---- load weights into SMEM (kernel is [K][C][F] = [kc][f] with C=F=32) ----
    for (int i = tid; i < SW_FLOATS; i += THREADS) sW[i] = kern[i];

    // ---- Phase 1: deformable bilinear sampling ----
    // warp w owns positions 8w..8w+7; lane = input channel c.
    #pragma unroll
    for (int p = 0; p < 8; ++p) {
        const int pos  = w * 8 + p;
        const int xcol = xbase + pos;
        const float* offp = off + ((y * WW + xcol) * KK) * 2;
        const int pp = pos >> 1;
        const int sub = (pos & 1) * 2;

        #pragma unroll
        for (int k = 0; k < KK; ++k) {
            const float2 o = __ldg((const float2*)(offp + 2 * k));
            // padded coordinates: tap base = (y + k/3, x + k%3), pad=1, bounds [0,385]
            float yf = fminf(fmaxf((float)(y + k / 3) + o.y, 0.f), 385.f);
            float xf = fminf(fmaxf((float)(xcol + k % 3) + o.x, 0.f), 385.f);
            const float y0f = floorf(yf), x0f = floorf(xf);
            const int y0 = (int)y0f, x0 = (int)x0f;
            const int y1 = min(y0 + 1, 385), x1 = min(x0 + 1, 385);
            const float wy0 = (float)y1 - yf, wy1 = yf - y0f;
            const float wx0 = (float)x1 - xf, wx1 = xf - x0f;
            const float w00 = wy0 * wx0, w01 = wy0 * wx1;
            const float w10 = wy1 * wx0, w11 = wy1 * wx1;

            // padded->unpadded: valid rows/cols are [1,384]; outside is zero pad
            const bool vy0 = (y0 >= 1) && (y0 <= 384);
            const bool vy1 = (y1 >= 1) && (y1 <= 384);
            const bool vx0 = (x0 >= 1) && (x0 <= 384);
            const bool vx1 = (x1 >= 1) && (x1 <= 384);

            const int i00 = ((y0 - 1) * WW + (x0 - 1)) * CC + lane;
            const int i01 = ((y0 - 1) * WW + (x1 - 1)) * CC + lane;
            const int i10 = ((y1 - 1) * WW + (x0 - 1)) * CC + lane;
            const int i11 = ((y1 - 1) * WW + (x1 - 1)) * CC + lane;
            const int B1 = HH * WW * CC;   // batch stride

            float a00 = 0.f, a01 = 0.f, a10 = 0.f, a11 = 0.f;  // batch 0
            float b00 = 0.f, b01 = 0.f, b10 = 0.f, b11 = 0.f;  // batch 1
            if (vy0 && vx0) { a00 = __ldg(x + i00); b00 = __ldg(x + B1 + i00); }
            if (vy0 && vx1) { a01 = __ldg(x + i01); b01 = __ldg(x + B1 + i01); }
            if (vy1 && vx0) { a10 = __ldg(x + i10); b10 = __ldg(x + B1 + i10); }
            if (vy1 && vx1) { a11 = __ldg(x + i11); b11 = __ldg(x + B1 + i11); }

            float s0 = w00 * a00;
            s0 = fmaf(w01, a01, s0); s0 = fmaf(w10, a10, s0); s0 = fmaf(w11, a11, s0);
            float s1 = w00 * b00;
            s1 = fmaf(w01, b01, s1); s1 = fmaf(w10, b10, s1); s1 = fmaf(w11, b11, s1);

            const int kc = k * 32 + lane;
            *(float2*)(pixS + ((pp * 288 + kc) * 4 + sub)) = make_float2(s0, s1);
        }
    }

    __syncthreads();

    // ---- Phase 2: contraction out[row][f] = sum_kc pix[row][kc] * W[kc][f] ----
    // lane = f. Warp w owns positions 8w..8w+7 (pos-pairs 4w..4w+3).
    // acc[2j+e] is packed (batch0, batch1) for position 8w + 2j + e.
    unsigned long long acc[8];
    #pragma unroll
    for (int i = 0; i < 8; ++i) acc[i] = 0ull;

    const float* pbase = pixS + (4 * w) * 288 * 4;

    #pragma unroll 8
    for (int kc = 0; kc < 288; ++kc) {
        const float wv = sW[kc * 32 + lane];
        const unsigned long long wd = pack2(wv, wv);
        #pragma unroll
        for (int j = 0; j < 4; ++j) {
            const ulonglong2 av = *(const ulonglong2*)(pbase + (j * 288 + kc) * 4);
            ffma2(acc[2 * j],     av.x, wd);
            ffma2(acc[2 * j + 1], av.y, wd);
        }
    }

    // ---- Epilogue ----
    const float bv = __ldg(bias + lane);
    #pragma unroll
    for (int j = 0; j < 4; ++j) {
        #pragma unroll
        for (int e = 0; e < 2; ++e) {
            float lo, hi;
            unpack2(acc[2 * j + e], lo, hi);
            const int col = xbase + w * 8 + 2 * j + e;
            out[((0 * HH + y) * WW + col) * FF + lane] = lo + bv;
            out[((1 * HH + y) * WW + col) * FF + lane] = hi + bv;
        }
    }
}

extern "C" void kernel_launch(void* const* d_in, const int* in_sizes, int n_in,
                              void* d_out, int out_size)
{
    (void)in_sizes; (void)n_in; (void)out_size;
    const float* x    = (const float*)d_in[0];
    const float* off  = (const float*)d_in[1];
    const float* kern = (const float*)d_in[2];
    const float* bias = (const float*)d_in[3];
    float* out = (float*)d_out;

    cudaFuncSetAttribute(deform_conv_kernel,
                         cudaFuncAttributeMaxDynamicSharedMemorySize, SMEM_BYTES);

    dim3 grid(WW / POS_PER_BLK, HH);
    deform_conv_kernel<<<grid, THREADS, SMEM_BYTES>>>(x, off, kern, bias, out);
}

// round 3
// speedup vs baseline: 1.4616x; 1.4616x over previous
#include <cuda_runtime.h>
#include <cuda_fp16.h>
#include <cstdint>

#define HH 384
#define WW 384
#define CC 32
#define FF 32
#define KK 9
#define POS_PER_BLK 64
#define THREADS 512

// A: 128 rows x K'=576 fp16 (hi,lo interleaved) = 1152 B/row
#define ROWB 1152u
#define SMEM_A_OFF 0u
#define A_BYTES (128u * ROWB)              // 147456
#define SMEM_B_OFF A_BYTES                 // 147456
#define B_BYTES (32u * ROWB)               // 36864
#define SMEM_TOTAL (A_BYTES + B_BYTES)     // 184320

__device__ __forceinline__ uint32_t smem_u32(const void* p) {
    uint32_t a;
    asm("{ .reg .u64 t; cvta.to.shared.u64 t, %1; cvt.u32.u64 %0, t; }" : "=r"(a) : "l"(p));
    return a;
}

// 16B-granular XOR swizzle within each 128B group of a row.
// addr(row, cb) = row*1152 + (cb & ~127) + ((((cb>>4)&7) ^ (row&7)) << 4) + (cb & 15)

#define LDMATRIX_X4(r0, r1, r2, r3, addr)                                   \
    asm volatile("ldmatrix.sync.aligned.m8n8.x4.shared.b16 {%0,%1,%2,%3}, [%4];" \
                 : "=r"(r0), "=r"(r1), "=r"(r2), "=r"(r3) : "r"(addr))

#define MMA16816(d, a0, a1, a2, a3, b0, b1)                                 \
    asm volatile("mma.sync.aligned.m16n8k16.row.col.f32.f16.f16.f32 "       \
                 "{%0,%1,%2,%3}, {%4,%5,%6,%7}, {%8,%9}, {%0,%1,%2,%3};"    \
                 : "+f"((d)[0]), "+f"((d)[1]), "+f"((d)[2]), "+f"((d)[3])   \
                 : "r"(a0), "r"(a1), "r"(a2), "r"(a3), "r"(b0), "r"(b1))

// fp32 -> packed (fp16 hi | fp16 lo) in one u32; hi in low half (even K' col)
__device__ __forceinline__ uint32_t hilo_f16(float s) {
    __half h = __float2half_rn(s);
    __half l = __float2half_rn(s - __half2float(h));
    __half2 p = __halves2half2(h, l);
    return *(uint32_t*)&p;
}

extern __shared__ char smem[];

__global__ __launch_bounds__(THREADS, 1)
void deform_conv_hmma(const float* __restrict__ x,
                      const float* __restrict__ off,
                      const float* __restrict__ kern,
                      const float* __restrict__ bias,
                      float* __restrict__ out)
{
    const uint32_t sbase = smem_u32(smem);
    const int tid  = threadIdx.x;
    const int lane = tid & 31;
    const int w    = tid >> 5;            // 16 warps
    const int y    = blockIdx.y;
    const int xbase = blockIdx.x * POS_PER_BLK;

    // ---- B fill: B[n=f][k' pair at kc] = (w16, w16), kc = k*32 + c ----
    // i: f fastest (coalesced LDG); store has benign 4-way STS conflicts.
    for (int i = tid; i < KK * CC * FF; i += THREADS) {
        const int f = i & 31;
        const int c = (i >> 5) & 31;
        const int k = i >> 10;
        const float wv = __ldg(kern + (k * 32 + c) * 32 + f);
        const __half wh = __float2half_rn(wv);
        const __half2 p = __halves2half2(wh, wh);
        const uint32_t addr = SMEM_B_OFF + (uint32_t)f * ROWB + (uint32_t)k * 128u +
                              ((((uint32_t)(c >> 2)) ^ ((uint32_t)f & 7u)) << 4) +
                              ((uint32_t)(c & 3)) * 4u;
        *(uint32_t*)(smem + addr) = *(uint32_t*)&p;
    }

    // ---- Phase 1: deformable bilinear sampling -> split-fp16 A tile ----
    // warp w owns positions 4w..4w+3; lane = input channel c.
    const int Bstride = HH * WW * CC;
    #pragma unroll 1
    for (int p = 0; p < 4; ++p) {
        const int pos  = w * 4 + p;
        const int xcol = xbase + pos;
        const float* offp = off + (size_t)(y * WW + xcol) * (KK * 2);
        const int r0 = pos;          // batch 0 row
        const int r1 = 64 + pos;     // batch 1 row

        #pragma unroll
        for (int k = 0; k < KK; ++k) {
            const float2 o = __ldg((const float2*)(offp + 2 * k));
            // padded coords: tap base (y + k/3, x + k%3), pad=1, clamp to [0,385]
            float yf = fminf(fmaxf((float)(y + k / 3) + o.y, 0.f), 385.f);
            float xf = fminf(fmaxf((float)(xcol + k % 3) + o.x, 0.f), 385.f);
            const float y0f = floorf(yf), x0f = floorf(xf);
            const int y0 = (int)y0f, x0 = (int)x0f;
            const int y1 = min(y0 + 1, 385), x1 = min(x0 + 1, 385);
            const float wy0 = (float)y1 - yf, wy1 = yf - y0f;
            const float wx0 = (float)x1 - xf, wx1 = xf - x0f;
            const float w00 = wy0 * wx0, w01 = wy0 * wx1;
            const float w10 = wy1 * wx0, w11 = wy1 * wx1;

            const bool vy0 = (y0 >= 1) && (y0 <= 384);
            const bool vy1 = (y1 >= 1) && (y1 <= 384);
            const bool vx0 = (x0 >= 1) && (x0 <= 384);
            const bool vx1 = (x1 >= 1) && (x1 <= 384);

            const int i00 = ((y0 - 1) * WW + (x0 - 1)) * CC + lane;
            const int i01 = ((y0 - 1) * WW + (x1 - 1)) * CC + lane;
            const int i10 = ((y1 - 1) * WW + (x0 - 1)) * CC + lane;
            const int i11 = ((y1 - 1) * WW + (x1 - 1)) * CC + lane;

            float a00 = 0.f, a01 = 0.f, a10 = 0.f, a11 = 0.f;  // batch 0
            float b00 = 0.f, b01 = 0.f, b10 = 0.f, b11 = 0.f;  // batch 1
            if (vy0 && vx0) { a00 = __ldg(x + i00); b00 = __ldg(x + Bstride + i00); }
            if (vy0 && vx1) { a01 = __ldg(x + i01); b01 = __ldg(x + Bstride + i01); }
            if (vy1 && vx0) { a10 = __ldg(x + i10); b10 = __ldg(x + Bstride + i10); }
            if (vy1 && vx1) { a11 = __ldg(x + i11); b11 = __ldg(x + Bstride + i11); }

            float s0 = w00 * a00;
            s0 = fmaf(w01, a01, s0); s0 = fmaf(w10, a10, s0); s0 = fmaf(w11, a11, s0);
            float s1 = w00 * b00;
            s1 = fmaf(w01, b01, s1); s1 = fmaf(w10, b10, s1); s1 = fmaf(w11, b11, s1);

            // A store: row r, cb = k*128 + lane*4  (conflict-free after swizzle)
            const uint32_t sub = (uint32_t)(lane >> 2);
            const uint32_t lo4 = ((uint32_t)(lane & 3)) * 4u;
            const uint32_t ad0 = SMEM_A_OFF + (uint32_t)r0 * ROWB + (uint32_t)k * 128u +
                                 ((sub ^ ((uint32_t)r0 & 7u)) << 4) + lo4;
            const uint32_t ad1 = SMEM_A_OFF + (uint32_t)r1 * ROWB + (uint32_t)k * 128u +
                                 ((sub ^ ((uint32_t)r1 & 7u)) << 4) + lo4;
            *(uint32_t*)(smem + ad0) = hilo_f16(s0);
            *(uint32_t*)(smem + ad1) = hilo_f16(s1);
        }
    }

    __syncthreads();

    // ---- Phase 2: HMMA GEMM. Warps 0..7: rows 16w..16w+15, all N=32 ----
    if (w < 8) {
        const int rowbase = w * 16;

        // ldmatrix lane roles
        const int rl  = rowbase + (lane & 7) + (lane & 8);  // A row for this lane
        const int kha = (lane >> 4) & 1;                    // A k-half (16B unit)
        const int nr0 = (lane & 7) + (((lane >> 4) & 1) << 3);        // B x4 #0 row
        const int nr1 = 16 + nr0;                                     // B x4 #1 row
        const int khb = (lane >> 3) & 1;                    // B k-half

        const uint32_t a_row  = sbase + SMEM_A_OFF + (uint32_t)rl * ROWB;
        const uint32_t b_row0 = sbase + SMEM_B_OFF + (uint32_t)nr0 * ROWB;
        const uint32_t b_row1 = sbase + SMEM_B_OFF + (uint32_t)nr1 * ROWB;
        const uint32_t amask = (uint32_t)rl & 7u;
        const uint32_t bmask0 = (uint32_t)nr0 & 7u;
        const uint32_t bmask1 = (uint32_t)nr1 & 7u;

        float d[16];
        #pragma unroll
        for (int i = 0; i < 16; ++i) d[i] = 0.f;

        #pragma unroll 2
        for (int s = 0; s < 36; ++s) {
            const uint32_t grp = (uint32_t)(s >> 2) * 128u;
            const uint32_t s2  = (uint32_t)(2 * s);

            uint32_t a0, a1, a2, a3;
            LDMATRIX_X4(a0, a1, a2, a3,
                        a_row + grp + ((((s2 + (uint32_t)kha) & 7u) ^ amask) << 4));
            uint32_t b0, b1, b2, b3;
            LDMATRIX_X4(b0, b1, b2, b3,
                        b_row0 + grp + ((((s2 + (uint32_t)khb) & 7u) ^ bmask0) << 4));
            uint32_t b4, b5, b6, b7;
            LDMATRIX_X4(b4, b5, b6, b7,
                        b_row1 + grp + ((((s2 + (uint32_t)khb) & 7u) ^ bmask1) << 4));

            MMA16816(d + 0,  a0, a1, a2, a3, b0, b1);   // n 0..7
            MMA16816(d + 4,  a0, a1, a2, a3, b2, b3);   // n 8..15
            MMA16816(d + 8,  a0, a1, a2, a3, b4, b5);   // n 16..23
            MMA16816(d + 12, a0, a1, a2, a3, b6, b7);   // n 24..31
        }

        // ---- Epilogue: D frag (row g(+8), col 2t(+1)) -> out[b][y][x][f] ----
        const int g = lane >> 2;
        const int t = lane & 3;
        const int R0 = rowbase + g;
        const int R1 = R0 + 8;
        const int b0r = R0 >> 6, p0r = R0 & 63;
        const int b1r = R1 >> 6, p1r = R1 & 63;
        float* o0 = out + ((size_t)(b0r * HH + y) * WW + xbase + p0r) * FF;
        float* o1 = out + ((size_t)(b1r * HH + y) * WW + xbase + p1r) * FF;

        #pragma unroll
        for (int nt = 0; nt < 4; ++nt) {
            const int f0 = nt * 8 + 2 * t;
            const float2 bv = __ldg((const float2*)(bias + f0));
            float2 v0 = make_float2(d[nt * 4 + 0] + bv.x, d[nt * 4 + 1] + bv.y);
            float2 v1 = make_float2(d[nt * 4 + 2] + bv.x, d[nt * 4 + 3] + bv.y);
            *(float2*)(o0 + f0) = v0;
            *(float2*)(o1 + f0) = v1;
        }
    }
}

extern "C" void kernel_launch(void* const* d_in, const int* in_sizes, int n_in,
                              void* d_out, int out_size)
{
    (void)in_sizes; (void)n_in; (void)out_size;
    const float* x    = (const float*)d_in[0];
    const float* off  = (const float*)d_in[1];
    const float* kern = (const float*)d_in[2];
    const float* bias = (const float*)d_in[3];
    float* out = (float*)d_out;

    cudaFuncSetAttribute(deform_conv_hmma,
                         cudaFuncAttributeMaxDynamicSharedMemorySize, SMEM_TOTAL);

    dim3 grid(WW / POS_PER_BLK, HH);
    deform_conv_hmma<<<grid, THREADS, SMEM_TOTAL>>>(x, off, kern, bias, out);
}